// round 15
// baseline (speedup 1.0000x reference)
#include <cuda_runtime.h>
#include <cuda_fp16.h>
#include <cstdint>

// ---------------------------------------------------------------------------
// Problem constants
// ---------------------------------------------------------------------------
#define MA      100001      // N_ATOMS + 1
#define MB      200001      // N_BONDS + 1
#define N_AT    100000
#define NMOL    2048
#define HID     300
#define AFD     133
#define BFD     147
#define MAXNB   6

#define NPAD    320         // compute width (weights, accumulators)
#define STR     304         // storage row stride (19 x 16; covers HID=300)
#define MBP     200064      // MB padded to 64
#define MAP     100096      // MA padded to 64
#define KCH0    10          // GEMM0: K=147 -> 160
#define KCH1    19          // GEMM1: K=300 -> 304
#define KCH2    28          // GEMM2: 9 planes f_atoms (144) + 19 planes amsg (304)

// ---------------------------------------------------------------------------
// Device buffers (static globals; no allocation anywhere)
// ---------------------------------------------------------------------------
__device__ __align__(16) __half g_fb16[(size_t)MBP * 160];      //  64 MB
__device__ __align__(16) __half g_fa16[(size_t)MAP * 144];      //  29 MB
__device__ __align__(16) __half g_pre [(size_t)MBP * STR];      // 122 MB
__device__ __align__(16) __half g_bmsg[(size_t)MB  * STR];      // 122 MB
__device__ __align__(16) __half g_amsg[(size_t)MAP * STR];      //  61 MB
__device__ __align__(16) __half g_binput16[(size_t)MB * STR];   // 122 MB
__device__ __align__(16) __half g_wt0[KCH0 * NPAD * 16];
__device__ __align__(16) __half g_wt1[KCH1 * NPAD * 16];
__device__ __align__(16) __half g_wt2[KCH2 * NPAD * 16];
__device__ float g_counts[NMOL];

// ---------------------------------------------------------------------------
// Helpers
// ---------------------------------------------------------------------------
__device__ __forceinline__ uint32_t smem_u32(const void* p) {
    uint32_t a;
    asm("{ .reg .u64 t; cvta.to.shared.u64 t, %1; cvt.u32.u64 %0, t; }"
        : "=r"(a) : "l"(p));
    return a;
}

#define CP_ASYNC16(dst, src) \
    asm volatile("cp.async.cg.shared.global [%0], [%1], 16;" :: "r"(dst), "l"(src) : "memory")
#define CP_COMMIT()  asm volatile("cp.async.commit_group;" ::: "memory")
template <int N>
__device__ __forceinline__ void cp_wait() {
    asm volatile("cp.async.wait_group %0;" :: "n"(N) : "memory");
}

#define LDSM_X4(r0, r1, r2, r3, addr) \
    asm volatile("ldmatrix.sync.aligned.m8n8.x4.shared.b16 {%0,%1,%2,%3}, [%4];" \
                 : "=r"(r0), "=r"(r1), "=r"(r2), "=r"(r3) : "r"(addr))

__device__ __forceinline__ void mma16816(float d[4], const uint32_t a[4],
                                         const uint32_t b[2]) {
    asm volatile(
        "mma.sync.aligned.m16n8k16.row.col.f32.f16.f16.f32 "
        "{%0,%1,%2,%3},{%4,%5,%6,%7},{%8,%9},{%0,%1,%2,%3};"
        : "+f"(d[0]), "+f"(d[1]), "+f"(d[2]), "+f"(d[3])
        : "r"(a[0]), "r"(a[1]), "r"(a[2]), "r"(a[3]), "r"(b[0]), "r"(b[1]));
}

// 16B-chunk XOR swizzle (conflict-free ldmatrix phases)
__device__ __forceinline__ int SWZ(int r) { return (r >> 2) & 1; }

// ---------------------------------------------------------------------------
// GEMM: block = 64 rows x 320 cols, 256 threads = 8 warps (2m x 4n).
// 8-stage cp.async pipeline, k-chunk = 16, 2 CTAs/SM.
// MODE 0: A=g_fb16          -> binput16=D            (bmsg write ELIMINATED;
//                              consumers recompute relu on the fly)
// MODE 1: A=g_pre           -> bmsg=relu(binput16+D)
// MODE 2: A=g_fa16|g_amsg   -> atomicAdd(out[mol], relu(D+bias))
// ---------------------------------------------------------------------------
#define STAGE_B 12288
#define NSTG    8
#define SMEM_T  (NSTG * STAGE_B)   // 98304
#define EPI_STRIDE 352   // halves; 704B/row -> conflict-free LDS.128

template <int MODE>
__device__ __forceinline__ void issue_stage(uint32_t sb, int kc, int m0, int tid)
{
    uint32_t base = sb + (uint32_t)(kc & (NSTG - 1)) * STAGE_B;
    const __half* wt = (MODE == 0) ? g_wt0 : (MODE == 1) ? g_wt1 : g_wt2;
#pragma unroll
    for (int it = 0; it < 3; it++) {
        int u = tid + it * 256;
        uint32_t dst;
        const __half* src;
        if (u < 128) {
            int r = u >> 1, sel = u & 1;
            int grow = m0 + r;
            if (MODE == 0)
                src = g_fb16 + (size_t)grow * 160 + kc * 16 + sel * 8;
            else if (MODE == 1)
                src = g_pre + (size_t)grow * STR + kc * 16 + sel * 8;
            else
                src = (kc < 9)
                    ? g_fa16 + (size_t)grow * 144 + kc * 16 + sel * 8
                    : g_amsg + (size_t)grow * STR + (kc - 9) * 16 + sel * 8;
            dst = base + (uint32_t)((r * 2 + (sel ^ SWZ(r))) * 16);
        } else {
            int v = u - 128;                         // 0..639
            src = wt + (size_t)kc * (NPAD * 16) + v * 8;
            dst = base + 2048 + (uint32_t)(v * 16);
        }
        CP_ASYNC16(dst, src);
    }
    CP_COMMIT();
}

template <int MODE, int KCH>
__global__ __launch_bounds__(256, 2)
void tc_gemm(int M, const float* __restrict__ bias,
             const int* __restrict__ mol_ids, float* __restrict__ out)
{
    extern __shared__ __align__(16) char smem[];
    const uint32_t sb = smem_u32(smem);
    const int tid  = threadIdx.x;
    const int lane = tid & 31;
    const int wid  = tid >> 5;
    const int wm   = wid & 1;
    const int wn   = wid >> 1;
    const int m0   = blockIdx.x * 64;

    // fragment ldmatrix offsets (bytes within a stage)
    uint32_t Aoff[2], Boff[5];
    {
        int sel = lane >> 4;
#pragma unroll
        for (int mf = 0; mf < 2; mf++) {
            int r = wm * 32 + mf * 16 + (lane & 15);
            Aoff[mf] = (uint32_t)((r * 2 + (sel ^ SWZ(r))) * 16);
        }
    }
    {
        int sel = (lane >> 3) & 1;
        int nb  = (lane & 7) + ((lane >> 4) & 1) * 8;
#pragma unroll
        for (int jp = 0; jp < 5; jp++) {
            int n = wn * 80 + jp * 16 + nb;
            Boff[jp] = (uint32_t)(2048 + (n * 2 + (sel ^ SWZ(n))) * 16);
        }
    }

    float acc[2][10][4];
#pragma unroll
    for (int mf = 0; mf < 2; mf++)
#pragma unroll
        for (int j = 0; j < 10; j++)
#pragma unroll
            for (int q = 0; q < 4; q++) acc[mf][j][q] = 0.f;

#pragma unroll
    for (int s = 0; s < 7; s++)
        issue_stage<MODE>(sb, s, m0, tid);

    for (int kc = 0; kc < KCH; kc++) {
        cp_wait<6>();
        __syncthreads();
        const uint32_t stg = sb + (uint32_t)(kc & (NSTG - 1)) * STAGE_B;

        uint32_t a[2][4];
#pragma unroll
        for (int mf = 0; mf < 2; mf++)
            LDSM_X4(a[mf][0], a[mf][1], a[mf][2], a[mf][3], stg + Aoff[mf]);
        uint32_t b[10][2];
#pragma unroll
        for (int jp = 0; jp < 5; jp++) {
            uint32_t r0, r1, r2, r3;
            LDSM_X4(r0, r1, r2, r3, stg + Boff[jp]);
            b[2 * jp][0] = r0; b[2 * jp][1] = r1;
            b[2 * jp + 1][0] = r2; b[2 * jp + 1][1] = r3;
        }

        if (kc + 7 < KCH) issue_stage<MODE>(sb, kc + 7, m0, tid);

#pragma unroll
        for (int mf = 0; mf < 2; mf++)
#pragma unroll
            for (int j = 0; j < 10; j++)
                mma16816(acc[mf][j], a[mf], b[j]);
    }

    // -------- epilogue --------
    if (MODE == 2) {
        const int g   = lane >> 2;
        const int tig = lane & 3;
#pragma unroll
        for (int mf = 0; mf < 2; mf++) {
#pragma unroll
            for (int h = 0; h < 2; h++) {
                int gm = m0 + wm * 32 + mf * 16 + g + h * 8;
                if (gm >= M) continue;
                int mol = -1;
                if (gm >= 1) mol = mol_ids[gm - 1];
                if (mol < 0) continue;
#pragma unroll
                for (int j = 0; j < 10; j++) {
                    int col = wn * 80 + j * 8 + tig * 2;
                    float vx = acc[mf][j][h * 2];
                    float vy = acc[mf][j][h * 2 + 1];
                    if (col < HID) {
                        atomicAdd(&out[(size_t)mol * HID + col],     fmaxf(vx + bias[col], 0.f));
                        atomicAdd(&out[(size_t)mol * HID + col + 1], fmaxf(vy + bias[col + 1], 0.f));
                    }
                }
            }
        }
    } else {
        // stage fp16 D in SMEM, then fully-coalesced vector I/O (38 chunks = 304 cols)
        __syncthreads();                   // all LDSM of last chunk done
        __half* sh = (__half*)smem;        // 64 x EPI_STRIDE halves = 45056 B
        const int g   = lane >> 2;
        const int tig = lane & 3;
#pragma unroll
        for (int mf = 0; mf < 2; mf++)
#pragma unroll
            for (int h = 0; h < 2; h++) {
                int rl = wm * 32 + mf * 16 + g + h * 8;
#pragma unroll
                for (int j = 0; j < 10; j++) {
                    int col = wn * 80 + j * 8 + tig * 2;
                    *(__half2*)&sh[rl * EPI_STRIDE + col] =
                        __floats2half2_rn(acc[mf][j][h * 2], acc[mf][j][h * 2 + 1]);
                }
            }
        __syncthreads();

        const int r  = tid >> 2;           // 0..63
        const int cp = tid & 3;
        const int gm = m0 + r;
        if (gm < M) {
            const __half2 z = __floats2half2_rn(0.f, 0.f);
#pragma unroll
            for (int i = 0; i < 10; i++) {
                int ch = cp + i * 4;       // 16B chunk index 0..37
                if (ch >= 38) break;
                uint4 d = *(uint4*)&sh[r * EPI_STRIDE + ch * 8];
                size_t o = (size_t)gm * STR + ch * 8;
                if (MODE == 0) {
                    *(uint4*)&g_binput16[o] = d;     // bmsg write eliminated
                } else {
                    uint4 bi = *(const uint4*)&g_binput16[o];
                    __half2* dp = (__half2*)&d;
                    __half2* bp = (__half2*)&bi;
                    uint4 rl; __half2* rp = (__half2*)&rl;
#pragma unroll
                    for (int q = 0; q < 4; q++)
                        rp[q] = __hmax2(__hadd2(bp[q], dp[q]), z);
                    *(uint4*)&g_bmsg[o] = rl;
                }
            }
        }
    }
}

// ---------------------------------------------------------------------------
// gather: amsg[a] = sum_j relu?(src[a2b[a][j]])   (fp32 accumulate, fp16 store)
// RELU=true reads binput16 (post-GEMM0); false reads bmsg.
// ---------------------------------------------------------------------------
template <bool RELU>
__global__ void gather_kernel(const int* __restrict__ a2b,
                              const __half* __restrict__ src)
{
    int atom = blockIdx.x * 6 + threadIdx.y;
    if (atom >= MA) return;
    int tx = threadIdx.x;                 // 0..37, 8 halves each
    const int* row = a2b + (size_t)atom * MAXNB;
    const __half2 z = __floats2half2_rn(0.f, 0.f);
    float2 acc[4] = {{0,0},{0,0},{0,0},{0,0}};
#pragma unroll
    for (int j = 0; j < MAXNB; j++) {
        uint4 v = *(const uint4*)(src + (size_t)row[j] * STR + tx * 8);
        __half2* hp = (__half2*)&v;
#pragma unroll
        for (int q = 0; q < 4; q++) {
            __half2 hv = RELU ? __hmax2(hp[q], z) : hp[q];
            float2 f = __half22float2(hv);
            acc[q].x += f.x; acc[q].y += f.y;
        }
    }
    uint4 u;
    __half2* up = (__half2*)&u;
#pragma unroll
    for (int q = 0; q < 4; q++) up[q] = __float22half2_rn(acc[q]);
    *(uint4*)(g_amsg + (size_t)atom * STR + tx * 8) = u;
}

// pre[m] = amsg[b2a[m]] - relu?(bsrc[b2revb[m]])
template <bool RELU>
__global__ void pre_kernel(const int* __restrict__ b2a, const int* __restrict__ b2revb,
                           const __half* __restrict__ bsrc)
{
    int bond = blockIdx.x * 6 + threadIdx.y;
    if (bond >= MB) return;
    int tx = threadIdx.x;
    int ia = b2a[bond], ib = b2revb[bond];
    uint4 va = *(const uint4*)(g_amsg + (size_t)ia * STR + tx * 8);
    uint4 vb = *(const uint4*)(bsrc + (size_t)ib * STR + tx * 8);
    const __half2 z = __floats2half2_rn(0.f, 0.f);
    __half2* ap = (__half2*)&va;
    __half2* bp = (__half2*)&vb;
    uint4 u; __half2* up = (__half2*)&u;
#pragma unroll
    for (int q = 0; q < 4; q++) {
        __half2 bv = RELU ? __hmax2(bp[q], z) : bp[q];
        up[q] = __hsub2(ap[q], bv);
    }
    *(uint4*)(g_pre + (size_t)bond * STR + tx * 8) = u;
}

// ---------------------------------------------------------------------------
// prep kernels
// ---------------------------------------------------------------------------
__global__ void prep_fb(const float* __restrict__ f_bonds)
{
    long i = blockIdx.x * 256L + threadIdx.x;
    if (i >= (long)MBP * 20) return;
    long m = i / 20; int t = (int)(i % 20);
    int k0 = t * 8;
    __half h[8];
#pragma unroll
    for (int q = 0; q < 8; q++) {
        int k = k0 + q;
        h[q] = (m < MB && k < BFD) ? __float2half_rn(f_bonds[m * BFD + k]) : __half(0.f);
    }
    *(uint4*)(g_fb16 + (size_t)m * 160 + k0) = *(uint4*)h;
}

__global__ void prep_fa(const float* __restrict__ f_atoms)
{
    long i = blockIdx.x * 256L + threadIdx.x;
    if (i >= (long)MAP * 18) return;
    long m = i / 18; int t = (int)(i % 18);
    int k0 = t * 8;
    __half h[8];
#pragma unroll
    for (int q = 0; q < 8; q++) {
        int k = k0 + q;
        h[q] = (m < MA && k < AFD) ? __float2half_rn(f_atoms[m * AFD + k]) : __half(0.f);
    }
    *(uint4*)(g_fa16 + (size_t)m * 144 + k0) = *(uint4*)h;
}

// weights: fp16, k-planar [plane][320][16], swizzle baked per n-row
__global__ void prep_w(const float* __restrict__ Wi, const float* __restrict__ Wh,
                       const float* __restrict__ Wo)
{
    int i = blockIdx.x * 256 + threadIdx.x;
    const int I0 = 320 * 2 * KCH0, I1 = 320 * 2 * KCH1, I2 = 320 * 2 * KCH2;
    if (i >= I0 + I1 + I2) return;
    const float* W; __half* dst; int n, t, which;
    if (i < I0)            { W = Wi; dst = g_wt0; n = i / (2*KCH0); t = i % (2*KCH0); which = 0; }
    else if (i < I0 + I1)  { int j = i - I0; W = Wh; dst = g_wt1; n = j / (2*KCH1); t = j % (2*KCH1); which = 1; }
    else                   { int j = i - I0 - I1; W = Wo; dst = g_wt2; n = j / (2*KCH2); t = j % (2*KCH2); which = 2; }
    int plane = t >> 1, sel = t & 1;
    __half h[8];
#pragma unroll
    for (int q = 0; q < 8; q++) {
        int kk = plane * 16 + sel * 8 + q;
        float v = 0.f;
        if (n < HID) {
            if (which == 0)      { if (kk < BFD) v = W[(size_t)kk * HID + n]; }
            else if (which == 1) { if (kk < HID) v = W[(size_t)kk * HID + n]; }
            else {
                if (plane < 9) { if (kk < AFD) v = W[(size_t)kk * HID + n]; }
                else {
                    int k2 = (plane - 9) * 16 + sel * 8 + q;
                    if (k2 < HID) v = W[(size_t)(AFD + k2) * HID + n];
                }
            }
        }
        h[q] = __float2half_rn(v);
    }
    *(uint4*)(dst + ((size_t)plane * NPAD + n) * 16 + (sel ^ SWZ(n)) * 8) = *(uint4*)h;
}

// ---------------------------------------------------------------------------
__global__ void zero_kernel(float* __restrict__ out)
{
    int i = blockIdx.x * 256 + threadIdx.x;
    if (i < NMOL * HID) out[i] = 0.f;
    if (i < NMOL) g_counts[i] = 0.f;
}
__global__ void count_kernel(const int* __restrict__ mol_ids)
{
    int i = blockIdx.x * 256 + threadIdx.x;
    if (i < N_AT) atomicAdd(&g_counts[mol_ids[i]], 1.f);
}
__global__ void divide_kernel(float* __restrict__ out)
{
    int i = blockIdx.x * 256 + threadIdx.x;
    if (i < NMOL * HID) out[i] = out[i] / fmaxf(g_counts[i / HID], 1.f);
}

// ---------------------------------------------------------------------------
extern "C" void kernel_launch(void* const* d_in, const int* in_sizes, int n_in,
                              void* d_out, int out_size)
{
    const float* f_atoms = (const float*)d_in[0];
    const float* f_bonds = (const float*)d_in[1];
    const float* W_i     = (const float*)d_in[2];
    const float* W_h     = (const float*)d_in[3];
    const float* W_o     = (const float*)d_in[4];
    const float* b_o     = (const float*)d_in[5];
    const int*   a2b     = (const int*)d_in[6];
    const int*   b2a     = (const int*)d_in[7];
    const int*   b2revb  = (const int*)d_in[8];
    const int*   mol_ids = (const int*)d_in[9];
    float* out = (float*)d_out;

    cudaFuncSetAttribute(tc_gemm<0, KCH0>, cudaFuncAttributeMaxDynamicSharedMemorySize, SMEM_T);
    cudaFuncSetAttribute(tc_gemm<1, KCH1>, cudaFuncAttributeMaxDynamicSharedMemorySize, SMEM_T);
    cudaFuncSetAttribute(tc_gemm<2, KCH2>, cudaFuncAttributeMaxDynamicSharedMemorySize, SMEM_T);

    __half *binp, *bmsg;
    cudaGetSymbolAddress((void**)&binp, g_binput16);
    cudaGetSymbolAddress((void**)&bmsg, g_bmsg);

    const int gridB = MBP / 64;       // 3126
    const int gridA = MAP / 64;       // 1564
    dim3 gblk(38, 6);
    const int ggA = (MA + 5) / 6;
    const int ggB = (MB + 5) / 6;
    const int wItems = 320 * 2 * (KCH0 + KCH1 + KCH2);

    // launch index 3 = tc_gemm<0> (the slot ncu samples)
    prep_fb<<<(int)(((long)MBP * 20 + 255) / 256), 256>>>(f_bonds);        // 0
    prep_w<<<(wItems + 255) / 256, 256>>>(W_i, W_h, W_o);                  // 1
    zero_kernel<<<(NMOL * HID + 255) / 256, 256>>>(out);                   // 2
    tc_gemm<0, KCH0><<<gridB, 256, SMEM_T>>>(MB, nullptr, nullptr, nullptr); // 3 <- profiled
    prep_fa<<<(int)(((long)MAP * 18 + 255) / 256), 256>>>(f_atoms);        // 4
    count_kernel<<<(N_AT + 255) / 256, 256>>>(mol_ids);                    // 5
    gather_kernel<true><<<ggA, gblk>>>(a2b, binp);                         // 6
    pre_kernel<true><<<ggB, gblk>>>(b2a, b2revb, binp);                    // 7
    tc_gemm<1, KCH1><<<gridB, 256, SMEM_T>>>(MB, nullptr, nullptr, nullptr); // 8
    gather_kernel<false><<<ggA, gblk>>>(a2b, bmsg);                        // 9
    pre_kernel<false><<<ggB, gblk>>>(b2a, b2revb, bmsg);                   // 10
    tc_gemm<1, KCH1><<<gridB, 256, SMEM_T>>>(MB, nullptr, nullptr, nullptr); // 11
    gather_kernel<false><<<ggA, gblk>>>(a2b, bmsg);                        // 12
    tc_gemm<2, KCH2><<<gridA, 256, SMEM_T>>>(MA, b_o, mol_ids, out);       // 13
    divide_kernel<<<(NMOL * HID + 255) / 256, 256>>>(out);                 // 14
}

// round 16
// speedup vs baseline: 1.0277x; 1.0277x over previous
#include <cuda_runtime.h>
#include <cuda_fp16.h>
#include <cstdint>

// ---------------------------------------------------------------------------
// Problem constants
// ---------------------------------------------------------------------------
#define MA      100001      // N_ATOMS + 1
#define MB      200001      // N_BONDS + 1
#define N_AT    100000
#define NMOL    2048
#define HID     300
#define AFD     133
#define BFD     147
#define MAXNB   6

#define NPAD    320         // compute + storage width (128B-aligned rows)
#define MBP     200064      // MB padded to 64
#define MAP     100096      // MA padded to 64
#define KCH0    10          // GEMM0: K=147 -> 160
#define KCH1    20          // GEMM1: K=300 -> 320
#define KCH2    29          // GEMM2: 9 planes f_atoms + 20 planes amsg

// ---------------------------------------------------------------------------
// Device buffers (static globals; no allocation anywhere)
// ---------------------------------------------------------------------------
__device__ __align__(16) __half g_fb16[(size_t)MBP * 160];      //  64 MB
__device__ __align__(16) __half g_fa16[(size_t)MAP * 144];      //  29 MB
__device__ __align__(16) __half g_pre [(size_t)MBP * NPAD];     // 128 MB
__device__ __align__(16) __half g_bmsg[(size_t)MB  * NPAD];     // 128 MB
__device__ __align__(16) __half g_amsg[(size_t)MAP * NPAD];     //  64 MB
__device__ __align__(16) __half g_binput16[(size_t)MB * NPAD];  // 128 MB
__device__ __align__(16) __half g_wt0[KCH0 * NPAD * 16];
__device__ __align__(16) __half g_wt1[KCH1 * NPAD * 16];
__device__ __align__(16) __half g_wt2[KCH2 * NPAD * 16];
__device__ float g_counts[NMOL];

// ---------------------------------------------------------------------------
// Helpers
// ---------------------------------------------------------------------------
__device__ __forceinline__ uint32_t smem_u32(const void* p) {
    uint32_t a;
    asm("{ .reg .u64 t; cvta.to.shared.u64 t, %1; cvt.u32.u64 %0, t; }"
        : "=r"(a) : "l"(p));
    return a;
}

#define CP_ASYNC16(dst, src) \
    asm volatile("cp.async.cg.shared.global [%0], [%1], 16;" :: "r"(dst), "l"(src) : "memory")
#define CP_COMMIT()  asm volatile("cp.async.commit_group;" ::: "memory")
template <int N>
__device__ __forceinline__ void cp_wait() {
    asm volatile("cp.async.wait_group %0;" :: "n"(N) : "memory");
}

#define LDSM_X4(r0, r1, r2, r3, addr) \
    asm volatile("ldmatrix.sync.aligned.m8n8.x4.shared.b16 {%0,%1,%2,%3}, [%4];" \
                 : "=r"(r0), "=r"(r1), "=r"(r2), "=r"(r3) : "r"(addr))

__device__ __forceinline__ void mma16816(float d[4], const uint32_t a[4],
                                         const uint32_t b[2]) {
    asm volatile(
        "mma.sync.aligned.m16n8k16.row.col.f32.f16.f16.f32 "
        "{%0,%1,%2,%3},{%4,%5,%6,%7},{%8,%9},{%0,%1,%2,%3};"
        : "+f"(d[0]), "+f"(d[1]), "+f"(d[2]), "+f"(d[3])
        : "r"(a[0]), "r"(a[1]), "r"(a[2]), "r"(a[3]), "r"(b[0]), "r"(b[1]));
}

// 16B-chunk XOR swizzle (conflict-free ldmatrix phases)
__device__ __forceinline__ int SWZ(int r) { return (r >> 2) & 1; }

// ---------------------------------------------------------------------------
// GEMM: block = 64 rows x 320 cols, 256 threads = 8 warps (2m x 4n).
// 8-stage cp.async pipeline, k-chunk = 16, 2 CTAs/SM.
// MODE 0: A=g_fb16          -> binput16=D   (bmsg write ELIMINATED; consumers
//                              recompute relu on the fly — value-identical)
// MODE 1: A=g_pre           -> bmsg=relu(binput16+D)
// MODE 2: A=g_fa16|g_amsg   -> atomicAdd(out[mol], relu(D+bias))
// ---------------------------------------------------------------------------
#define STAGE_B 12288
#define NSTG    8
#define SMEM_T  (NSTG * STAGE_B)   // 98304
#define EPI_STRIDE 352   // halves; 704B/row -> conflict-free LDS.128

template <int MODE>
__device__ __forceinline__ void issue_stage(uint32_t sb, int kc, int m0, int tid)
{
    uint32_t base = sb + (uint32_t)(kc & (NSTG - 1)) * STAGE_B;
    const __half* wt = (MODE == 0) ? g_wt0 : (MODE == 1) ? g_wt1 : g_wt2;
#pragma unroll
    for (int it = 0; it < 3; it++) {
        int u = tid + it * 256;
        uint32_t dst;
        const __half* src;
        if (u < 128) {
            int r = u >> 1, sel = u & 1;
            int grow = m0 + r;
            if (MODE == 0)
                src = g_fb16 + (size_t)grow * 160 + kc * 16 + sel * 8;
            else if (MODE == 1)
                src = g_pre + (size_t)grow * NPAD + kc * 16 + sel * 8;
            else
                src = (kc < 9)
                    ? g_fa16 + (size_t)grow * 144 + kc * 16 + sel * 8
                    : g_amsg + (size_t)grow * NPAD + (kc - 9) * 16 + sel * 8;
            dst = base + (uint32_t)((r * 2 + (sel ^ SWZ(r))) * 16);
        } else {
            int v = u - 128;                         // 0..639
            src = wt + (size_t)kc * (NPAD * 16) + v * 8;
            dst = base + 2048 + (uint32_t)(v * 16);
        }
        CP_ASYNC16(dst, src);
    }
    CP_COMMIT();
}

template <int MODE, int KCH>
__global__ __launch_bounds__(256, 2)
void tc_gemm(int M, const float* __restrict__ bias,
             const int* __restrict__ mol_ids, float* __restrict__ out)
{
    extern __shared__ __align__(16) char smem[];
    const uint32_t sb = smem_u32(smem);
    const int tid  = threadIdx.x;
    const int lane = tid & 31;
    const int wid  = tid >> 5;
    const int wm   = wid & 1;
    const int wn   = wid >> 1;
    const int m0   = blockIdx.x * 64;

    // fragment ldmatrix offsets (bytes within a stage)
    uint32_t Aoff[2], Boff[5];
    {
        int sel = lane >> 4;
#pragma unroll
        for (int mf = 0; mf < 2; mf++) {
            int r = wm * 32 + mf * 16 + (lane & 15);
            Aoff[mf] = (uint32_t)((r * 2 + (sel ^ SWZ(r))) * 16);
        }
    }
    {
        int sel = (lane >> 3) & 1;
        int nb  = (lane & 7) + ((lane >> 4) & 1) * 8;
#pragma unroll
        for (int jp = 0; jp < 5; jp++) {
            int n = wn * 80 + jp * 16 + nb;
            Boff[jp] = (uint32_t)(2048 + (n * 2 + (sel ^ SWZ(n))) * 16);
        }
    }

    float acc[2][10][4];
#pragma unroll
    for (int mf = 0; mf < 2; mf++)
#pragma unroll
        for (int j = 0; j < 10; j++)
#pragma unroll
            for (int q = 0; q < 4; q++) acc[mf][j][q] = 0.f;

#pragma unroll
    for (int s = 0; s < 7; s++)
        issue_stage<MODE>(sb, s, m0, tid);

    for (int kc = 0; kc < KCH; kc++) {
        cp_wait<6>();
        __syncthreads();
        const uint32_t stg = sb + (uint32_t)(kc & (NSTG - 1)) * STAGE_B;

        uint32_t a[2][4];
#pragma unroll
        for (int mf = 0; mf < 2; mf++)
            LDSM_X4(a[mf][0], a[mf][1], a[mf][2], a[mf][3], stg + Aoff[mf]);
        uint32_t b[10][2];
#pragma unroll
        for (int jp = 0; jp < 5; jp++) {
            uint32_t r0, r1, r2, r3;
            LDSM_X4(r0, r1, r2, r3, stg + Boff[jp]);
            b[2 * jp][0] = r0; b[2 * jp][1] = r1;
            b[2 * jp + 1][0] = r2; b[2 * jp + 1][1] = r3;
        }

        if (kc + 7 < KCH) issue_stage<MODE>(sb, kc + 7, m0, tid);

#pragma unroll
        for (int mf = 0; mf < 2; mf++)
#pragma unroll
            for (int j = 0; j < 10; j++)
                mma16816(acc[mf][j], a[mf], b[j]);
    }

    // -------- epilogue --------
    if (MODE == 2) {
        const int g   = lane >> 2;
        const int tig = lane & 3;
#pragma unroll
        for (int mf = 0; mf < 2; mf++) {
#pragma unroll
            for (int h = 0; h < 2; h++) {
                int gm = m0 + wm * 32 + mf * 16 + g + h * 8;
                if (gm >= M) continue;
                int mol = -1;
                if (gm >= 1) mol = mol_ids[gm - 1];
                if (mol < 0) continue;
#pragma unroll
                for (int j = 0; j < 10; j++) {
                    int col = wn * 80 + j * 8 + tig * 2;
                    float vx = acc[mf][j][h * 2];
                    float vy = acc[mf][j][h * 2 + 1];
                    if (col < HID) {
                        atomicAdd(&out[(size_t)mol * HID + col],     fmaxf(vx + bias[col], 0.f));
                        atomicAdd(&out[(size_t)mol * HID + col + 1], fmaxf(vy + bias[col + 1], 0.f));
                    }
                }
            }
        }
    } else {
        // stage fp16 D in SMEM, then fully-coalesced vector I/O
        __syncthreads();                   // all LDSM of last chunk done
        __half* sh = (__half*)smem;        // 64 x EPI_STRIDE halves = 45056 B
        const int g   = lane >> 2;
        const int tig = lane & 3;
#pragma unroll
        for (int mf = 0; mf < 2; mf++)
#pragma unroll
            for (int h = 0; h < 2; h++) {
                int rl = wm * 32 + mf * 16 + g + h * 8;
#pragma unroll
                for (int j = 0; j < 10; j++) {
                    int col = wn * 80 + j * 8 + tig * 2;
                    *(__half2*)&sh[rl * EPI_STRIDE + col] =
                        __floats2half2_rn(acc[mf][j][h * 2], acc[mf][j][h * 2 + 1]);
                }
            }
        __syncthreads();

        const int r  = tid >> 2;           // 0..63
        const int cp = tid & 3;
        const int gm = m0 + r;
        if (gm < M) {
            const __half2 z = __floats2half2_rn(0.f, 0.f);
#pragma unroll
            for (int i = 0; i < 10; i++) {
                int ch = cp + i * 4;       // 16B chunk index 0..39
                uint4 d = *(uint4*)&sh[r * EPI_STRIDE + ch * 8];
                size_t o = (size_t)gm * NPAD + ch * 8;
                if (MODE == 0) {
                    *(uint4*)&g_binput16[o] = d;     // bmsg write eliminated
                } else {
                    uint4 bi = *(const uint4*)&g_binput16[o];
                    __half2* dp = (__half2*)&d;
                    __half2* bp = (__half2*)&bi;
                    uint4 rl; __half2* rp = (__half2*)&rl;
#pragma unroll
                    for (int q = 0; q < 4; q++)
                        rp[q] = __hmax2(__hadd2(bp[q], dp[q]), z);
                    *(uint4*)&g_bmsg[o] = rl;
                }
            }
        }
    }
}

// ---------------------------------------------------------------------------
// gather: amsg[a] = sum_j relu?(src[a2b[a][j]])   (fp32 accumulate, fp16 store)
// RELU=true reads binput16 (post-GEMM0); false reads bmsg.
// ---------------------------------------------------------------------------
template <bool RELU>
__global__ void gather_kernel(const int* __restrict__ a2b,
                              const __half* __restrict__ src)
{
    int atom = blockIdx.x * 6 + threadIdx.y;
    if (atom >= MA) return;
    int tx = threadIdx.x;                 // 0..39, 8 halves each
    const int* row = a2b + (size_t)atom * MAXNB;
    const __half2 z = __floats2half2_rn(0.f, 0.f);
    float2 acc[4] = {{0,0},{0,0},{0,0},{0,0}};
#pragma unroll
    for (int j = 0; j < MAXNB; j++) {
        uint4 v = *(const uint4*)(src + (size_t)row[j] * NPAD + tx * 8);
        __half2* hp = (__half2*)&v;
#pragma unroll
        for (int q = 0; q < 4; q++) {
            __half2 hv = RELU ? __hmax2(hp[q], z) : hp[q];
            float2 f = __half22float2(hv);
            acc[q].x += f.x; acc[q].y += f.y;
        }
    }
    uint4 u;
    __half2* up = (__half2*)&u;
#pragma unroll
    for (int q = 0; q < 4; q++) up[q] = __float22half2_rn(acc[q]);
    *(uint4*)(g_amsg + (size_t)atom * NPAD + tx * 8) = u;
}

// pre[m] = amsg[b2a[m]] - relu?(bsrc[b2revb[m]])
template <bool RELU>
__global__ void pre_kernel(const int* __restrict__ b2a, const int* __restrict__ b2revb,
                           const __half* __restrict__ bsrc)
{
    int bond = blockIdx.x * 6 + threadIdx.y;
    if (bond >= MB) return;
    int tx = threadIdx.x;
    int ia = b2a[bond], ib = b2revb[bond];
    uint4 va = *(const uint4*)(g_amsg + (size_t)ia * NPAD + tx * 8);
    uint4 vb = *(const uint4*)(bsrc + (size_t)ib * NPAD + tx * 8);
    const __half2 z = __floats2half2_rn(0.f, 0.f);
    __half2* ap = (__half2*)&va;
    __half2* bp = (__half2*)&vb;
    uint4 u; __half2* up = (__half2*)&u;
#pragma unroll
    for (int q = 0; q < 4; q++) {
        __half2 bv = RELU ? __hmax2(bp[q], z) : bp[q];
        up[q] = __hsub2(ap[q], bv);
    }
    *(uint4*)(g_pre + (size_t)bond * NPAD + tx * 8) = u;
}

// ---------------------------------------------------------------------------
// prep kernels
// ---------------------------------------------------------------------------
__global__ void prep_fb(const float* __restrict__ f_bonds)
{
    long i = blockIdx.x * 256L + threadIdx.x;
    if (i >= (long)MBP * 20) return;
    long m = i / 20; int t = (int)(i % 20);
    int k0 = t * 8;
    __half h[8];
#pragma unroll
    for (int q = 0; q < 8; q++) {
        int k = k0 + q;
        h[q] = (m < MB && k < BFD) ? __float2half_rn(f_bonds[m * BFD + k]) : __half(0.f);
    }
    *(uint4*)(g_fb16 + (size_t)m * 160 + k0) = *(uint4*)h;
}

__global__ void prep_fa(const float* __restrict__ f_atoms)
{
    long i = blockIdx.x * 256L + threadIdx.x;
    if (i >= (long)MAP * 18) return;
    long m = i / 18; int t = (int)(i % 18);
    int k0 = t * 8;
    __half h[8];
#pragma unroll
    for (int q = 0; q < 8; q++) {
        int k = k0 + q;
        h[q] = (m < MA && k < AFD) ? __float2half_rn(f_atoms[m * AFD + k]) : __half(0.f);
    }
    *(uint4*)(g_fa16 + (size_t)m * 144 + k0) = *(uint4*)h;
}

// weights: fp16, k-planar [plane][320][16], swizzle baked per n-row
__global__ void prep_w(const float* __restrict__ Wi, const float* __restrict__ Wh,
                       const float* __restrict__ Wo)
{
    int i = blockIdx.x * 256 + threadIdx.x;
    const int I0 = 320 * 2 * KCH0, I1 = 320 * 2 * KCH1, I2 = 320 * 2 * KCH2;
    if (i >= I0 + I1 + I2) return;
    const float* W; __half* dst; int n, t, which;
    if (i < I0)            { W = Wi; dst = g_wt0; n = i / (2*KCH0); t = i % (2*KCH0); which = 0; }
    else if (i < I0 + I1)  { int j = i - I0; W = Wh; dst = g_wt1; n = j / (2*KCH1); t = j % (2*KCH1); which = 1; }
    else                   { int j = i - I0 - I1; W = Wo; dst = g_wt2; n = j / (2*KCH2); t = j % (2*KCH2); which = 2; }
    int plane = t >> 1, sel = t & 1;
    __half h[8];
#pragma unroll
    for (int q = 0; q < 8; q++) {
        int kk = plane * 16 + sel * 8 + q;
        float v = 0.f;
        if (n < HID) {
            if (which == 0)      { if (kk < BFD) v = W[(size_t)kk * HID + n]; }
            else if (which == 1) { if (kk < HID) v = W[(size_t)kk * HID + n]; }
            else {
                if (plane < 9) { if (kk < AFD) v = W[(size_t)kk * HID + n]; }
                else {
                    int k2 = (plane - 9) * 16 + sel * 8 + q;
                    if (k2 < HID) v = W[(size_t)(AFD + k2) * HID + n];
                }
            }
        }
        h[q] = __float2half_rn(v);
    }
    *(uint4*)(dst + ((size_t)plane * NPAD + n) * 16 + (sel ^ SWZ(n)) * 8) = *(uint4*)h;
}

// ---------------------------------------------------------------------------
__global__ void zero_kernel(float* __restrict__ out)
{
    int i = blockIdx.x * 256 + threadIdx.x;
    if (i < NMOL * HID) out[i] = 0.f;
    if (i < NMOL) g_counts[i] = 0.f;
}
__global__ void count_kernel(const int* __restrict__ mol_ids)
{
    int i = blockIdx.x * 256 + threadIdx.x;
    if (i < N_AT) atomicAdd(&g_counts[mol_ids[i]], 1.f);
}
__global__ void divide_kernel(float* __restrict__ out)
{
    int i = blockIdx.x * 256 + threadIdx.x;
    if (i < NMOL * HID) out[i] = out[i] / fmaxf(g_counts[i / HID], 1.f);
}

// ---------------------------------------------------------------------------
extern "C" void kernel_launch(void* const* d_in, const int* in_sizes, int n_in,
                              void* d_out, int out_size)
{
    const float* f_atoms = (const float*)d_in[0];
    const float* f_bonds = (const float*)d_in[1];
    const float* W_i     = (const float*)d_in[2];
    const float* W_h     = (const float*)d_in[3];
    const float* W_o     = (const float*)d_in[4];
    const float* b_o     = (const float*)d_in[5];
    const int*   a2b     = (const int*)d_in[6];
    const int*   b2a     = (const int*)d_in[7];
    const int*   b2revb  = (const int*)d_in[8];
    const int*   mol_ids = (const int*)d_in[9];
    float* out = (float*)d_out;

    cudaFuncSetAttribute(tc_gemm<0, KCH0>, cudaFuncAttributeMaxDynamicSharedMemorySize, SMEM_T);
    cudaFuncSetAttribute(tc_gemm<1, KCH1>, cudaFuncAttributeMaxDynamicSharedMemorySize, SMEM_T);
    cudaFuncSetAttribute(tc_gemm<2, KCH2>, cudaFuncAttributeMaxDynamicSharedMemorySize, SMEM_T);

    __half *binp, *bmsg;
    cudaGetSymbolAddress((void**)&binp, g_binput16);
    cudaGetSymbolAddress((void**)&bmsg, g_bmsg);

    const int gridB = MBP / 64;       // 3126
    const int gridA = MAP / 64;       // 1564
    dim3 gblk(40, 6);
    const int ggA = (MA + 5) / 6;
    const int ggB = (MB + 5) / 6;
    const int wItems = 320 * 2 * (KCH0 + KCH1 + KCH2);

    // launch index 3 = tc_gemm<0> (the slot ncu samples)
    prep_fb<<<(int)(((long)MBP * 20 + 255) / 256), 256>>>(f_bonds);        // 0
    prep_w<<<(wItems + 255) / 256, 256>>>(W_i, W_h, W_o);                  // 1
    zero_kernel<<<(NMOL * HID + 255) / 256, 256>>>(out);                   // 2
    tc_gemm<0, KCH0><<<gridB, 256, SMEM_T>>>(MB, nullptr, nullptr, nullptr); // 3 <- profiled
    prep_fa<<<(int)(((long)MAP * 18 + 255) / 256), 256>>>(f_atoms);        // 4
    count_kernel<<<(N_AT + 255) / 256, 256>>>(mol_ids);                    // 5
    gather_kernel<true><<<ggA, gblk>>>(a2b, binp);                         // 6
    pre_kernel<true><<<ggB, gblk>>>(b2a, b2revb, binp);                    // 7
    tc_gemm<1, KCH1><<<gridB, 256, SMEM_T>>>(MB, nullptr, nullptr, nullptr); // 8
    gather_kernel<false><<<ggA, gblk>>>(a2b, bmsg);                        // 9
    pre_kernel<false><<<ggB, gblk>>>(b2a, b2revb, bmsg);                   // 10
    tc_gemm<1, KCH1><<<gridB, 256, SMEM_T>>>(MB, nullptr, nullptr, nullptr); // 11
    gather_kernel<false><<<ggA, gblk>>>(a2b, bmsg);                        // 12
    tc_gemm<2, KCH2><<<gridA, 256, SMEM_T>>>(MA, b_o, mol_ids, out);       // 13
    divide_kernel<<<(NMOL * HID + 255) / 256, 256>>>(out);                 // 14
}

// round 17
// speedup vs baseline: 1.1037x; 1.0740x over previous
#include <cuda_runtime.h>
#include <cuda_fp16.h>
#include <cstdint>

// ---------------------------------------------------------------------------
// Problem constants
// ---------------------------------------------------------------------------
#define MA      100001      // N_ATOMS + 1
#define MB      200001      // N_BONDS + 1
#define N_AT    100000
#define NMOL    2048
#define HID     300
#define AFD     133
#define BFD     147
#define MAXNB   6

#define NPAD    320         // row stride (128B aligned)
#define MBP     200064      // MB padded to 64
#define MAP     100096      // MA padded to 64
#define KCH0    10          // GEMM0: K=147 -> 160
#define KCH1    20          // GEMM1: K=300 -> 320
#define KCH2    29          // GEMM2: 9 planes f_atoms + 20 planes amsg

// ---------------------------------------------------------------------------
// Device buffers (static globals; no allocation anywhere)
// ---------------------------------------------------------------------------
__device__ __align__(16) __half g_fb16[(size_t)MBP * 160];      //  64 MB
__device__ __align__(16) __half g_fa16[(size_t)MAP * 144];      //  29 MB
__device__ __align__(16) __half g_bmsgA[(size_t)MB * NPAD];     // 128 MB
__device__ __align__(16) __half g_bmsgB[(size_t)MB * NPAD];     // 128 MB
__device__ __align__(16) __half g_amsg[(size_t)MAP * NPAD];     //  64 MB
__device__ __align__(16) __half g_binput16[(size_t)MB * NPAD];  // 128 MB
__device__ __align__(16) __half g_wt0[KCH0 * NPAD * 16];
__device__ __align__(16) __half g_wt1[KCH1 * NPAD * 16];
__device__ __align__(16) __half g_wt2[KCH2 * NPAD * 16];
__device__ float g_counts[NMOL];

// ---------------------------------------------------------------------------
// Helpers
// ---------------------------------------------------------------------------
__device__ __forceinline__ uint32_t smem_u32(const void* p) {
    uint32_t a;
    asm("{ .reg .u64 t; cvta.to.shared.u64 t, %1; cvt.u32.u64 %0, t; }"
        : "=r"(a) : "l"(p));
    return a;
}

#define CP_ASYNC16(dst, src) \
    asm volatile("cp.async.cg.shared.global [%0], [%1], 16;" :: "r"(dst), "l"(src) : "memory")
#define CP_COMMIT()  asm volatile("cp.async.commit_group;" ::: "memory")
template <int N>
__device__ __forceinline__ void cp_wait() {
    asm volatile("cp.async.wait_group %0;" :: "n"(N) : "memory");
}

#define LDSM_X4(r0, r1, r2, r3, addr) \
    asm volatile("ldmatrix.sync.aligned.m8n8.x4.shared.b16 {%0,%1,%2,%3}, [%4];" \
                 : "=r"(r0), "=r"(r1), "=r"(r2), "=r"(r3) : "r"(addr))

__device__ __forceinline__ void mma16816(float d[4], const uint32_t a[4],
                                         const uint32_t b[2]) {
    asm volatile(
        "mma.sync.aligned.m16n8k16.row.col.f32.f16.f16.f32 "
        "{%0,%1,%2,%3},{%4,%5,%6,%7},{%8,%9},{%0,%1,%2,%3};"
        : "+f"(d[0]), "+f"(d[1]), "+f"(d[2]), "+f"(d[3])
        : "r"(a[0]), "r"(a[1]), "r"(a[2]), "r"(a[3]), "r"(b[0]), "r"(b[1]));
}

// 16B-chunk XOR swizzle (conflict-free ldmatrix phases)
__device__ __forceinline__ int SWZ(int r) { return (r >> 2) & 1; }

// ---------------------------------------------------------------------------
// GEMM: block = 64 rows x 320 cols, 256 threads = 8 warps (2m x 4n).
// 6-stage cp.async pipeline (14336 B/stage: A1 2K | A2 2K | B 10K), 2 CTAs/SM.
// MODE 0: A=g_fb16 (A1 only)       -> binput16=D
// MODE 1: A = A1 - [relu?]A2 computed at FRAGMENT time, where
//         A1 = amsg[b2a[m]], A2 = bSrc[b2revb[m]] (both cp.async gathered).
//         out: dst = relu(binput16 + D).  (pre kernel + buffer eliminated;
//         ping-pong bSrc/dst prevents the R8 read/write race)
// MODE 2: A=g_fa16|g_amsg (A1)     -> atomicAdd(out[mol], relu(D+bias))
// ---------------------------------------------------------------------------
#define STAGE_B 14336
#define NSTG    6
#define SMEM_T  (NSTG * STAGE_B)   // 86016
#define EPI_STRIDE 352   // halves; conflict-free LDS.128

template <int MODE>
__device__ __forceinline__ void issue_stage(uint32_t sb, int kc, int m0, int tid,
                                            const __half* pa, const __half* pb)
{
    uint32_t base = sb + (uint32_t)(kc % NSTG) * STAGE_B;
    const __half* wt = (MODE == 0) ? g_wt0 : (MODE == 1) ? g_wt1 : g_wt2;
    if (tid < 128) {
        int r = tid >> 1, sel = tid & 1;
        uint32_t adst = base + (uint32_t)((r * 2 + (sel ^ SWZ(r))) * 16);
        if (MODE == 1) {
            CP_ASYNC16(adst, pa + kc * 16);                 // A1: amsg[b2a]
            CP_ASYNC16(adst + 2048, pb + kc * 16);          // A2: bSrc[b2revb]
        } else {
            int grow = m0 + r;
            const __half* src;
            if (MODE == 0)
                src = g_fb16 + (size_t)grow * 160 + kc * 16 + sel * 8;
            else
                src = (kc < 9)
                    ? g_fa16 + (size_t)grow * 144 + kc * 16 + sel * 8
                    : g_amsg + (size_t)grow * NPAD + (kc - 9) * 16 + sel * 8;
            CP_ASYNC16(adst, src);
        }
    } else {
        int v = tid - 128;                                  // 0..127
        CP_ASYNC16(base + 4096 + (uint32_t)(v * 16),
                   wt + (size_t)kc * (NPAD * 16) + v * 8);
    }
    // B chunks 128..639
#pragma unroll
    for (int it = 1; it < 3; it++) {
        int v = tid + it * 256 - 128;                       // 128..639
        CP_ASYNC16(base + 4096 + (uint32_t)(v * 16),
                   wt + (size_t)kc * (NPAD * 16) + v * 8);
    }
    CP_COMMIT();
}

template <int MODE, int KCH, bool BRELU>
__global__ __launch_bounds__(256, 2)
void tc_gemm(int M, const float* __restrict__ bias,
             const int* __restrict__ mol_ids, float* __restrict__ out,
             const int* __restrict__ b2a, const int* __restrict__ b2revb,
             const __half* __restrict__ bSrc,   // MODE1: gathered subtrahend
             __half* __restrict__ dst)          // MODE0/1 output buffer
{
    extern __shared__ __align__(16) char smem[];
    const uint32_t sb = smem_u32(smem);
    const int tid  = threadIdx.x;
    const int lane = tid & 31;
    const int wid  = tid >> 5;
    const int wm   = wid & 1;
    const int wn   = wid >> 1;
    const int m0   = blockIdx.x * 64;

    // MODE1 gather pointers (per loader thread)
    const __half *pa = nullptr, *pb = nullptr;
    if (MODE == 1 && tid < 128) {
        int r = tid >> 1, sel = tid & 1;
        int gm = m0 + r;
        int idx = (gm < M) ? gm : 0;
        pa = g_amsg + (size_t)b2a[idx] * NPAD + sel * 8;
        pb = bSrc  + (size_t)b2revb[idx] * NPAD + sel * 8;
    }

    // fragment ldmatrix offsets (bytes within a stage)
    uint32_t Aoff[2], Boff[5];
    {
        int sel = lane >> 4;
#pragma unroll
        for (int mf = 0; mf < 2; mf++) {
            int r = wm * 32 + mf * 16 + (lane & 15);
            Aoff[mf] = (uint32_t)((r * 2 + (sel ^ SWZ(r))) * 16);
        }
    }
    {
        int sel = (lane >> 3) & 1;
        int nb  = (lane & 7) + ((lane >> 4) & 1) * 8;
#pragma unroll
        for (int jp = 0; jp < 5; jp++) {
            int n = wn * 80 + jp * 16 + nb;
            Boff[jp] = (uint32_t)(4096 + (n * 2 + (sel ^ SWZ(n))) * 16);
        }
    }

    float acc[2][10][4];
#pragma unroll
    for (int mf = 0; mf < 2; mf++)
#pragma unroll
        for (int j = 0; j < 10; j++)
#pragma unroll
            for (int q = 0; q < 4; q++) acc[mf][j][q] = 0.f;

#pragma unroll
    for (int s = 0; s < 5; s++)
        if (s < KCH) issue_stage<MODE>(sb, s, m0, tid, pa, pb);

    const __half2 hz = __floats2half2_rn(0.f, 0.f);

    for (int kc = 0; kc < KCH; kc++) {
        cp_wait<4>();
        __syncthreads();
        const uint32_t stg = sb + (uint32_t)(kc % NSTG) * STAGE_B;

        uint32_t a[2][4];
#pragma unroll
        for (int mf = 0; mf < 2; mf++) {
            if (MODE == 1) {
                uint32_t x[4], y[4];
                LDSM_X4(x[0], x[1], x[2], x[3], stg + Aoff[mf]);
                LDSM_X4(y[0], y[1], y[2], y[3], stg + 2048 + Aoff[mf]);
#pragma unroll
                for (int q = 0; q < 4; q++) {
                    __half2 hx = *(__half2*)&x[q];
                    __half2 hy = *(__half2*)&y[q];
                    if (BRELU) hy = __hmax2(hy, hz);
                    __half2 hr = __hsub2(hx, hy);
                    a[mf][q] = *(uint32_t*)&hr;
                }
            } else {
                LDSM_X4(a[mf][0], a[mf][1], a[mf][2], a[mf][3], stg + Aoff[mf]);
            }
        }
        uint32_t b[10][2];
#pragma unroll
        for (int jp = 0; jp < 5; jp++) {
            uint32_t r0, r1, r2, r3;
            LDSM_X4(r0, r1, r2, r3, stg + Boff[jp]);
            b[2 * jp][0] = r0; b[2 * jp][1] = r1;
            b[2 * jp + 1][0] = r2; b[2 * jp + 1][1] = r3;
        }

        if (kc + 5 < KCH) issue_stage<MODE>(sb, kc + 5, m0, tid, pa, pb);

#pragma unroll
        for (int mf = 0; mf < 2; mf++)
#pragma unroll
            for (int j = 0; j < 10; j++)
                mma16816(acc[mf][j], a[mf], b[j]);
    }

    // -------- epilogue --------
    if (MODE == 2) {
        const int g   = lane >> 2;
        const int tig = lane & 3;
#pragma unroll
        for (int mf = 0; mf < 2; mf++) {
#pragma unroll
            for (int h = 0; h < 2; h++) {
                int gm = m0 + wm * 32 + mf * 16 + g + h * 8;
                if (gm >= M) continue;
                int mol = -1;
                if (gm >= 1) mol = mol_ids[gm - 1];
                if (mol < 0) continue;
#pragma unroll
                for (int j = 0; j < 10; j++) {
                    int col = wn * 80 + j * 8 + tig * 2;
                    float vx = acc[mf][j][h * 2];
                    float vy = acc[mf][j][h * 2 + 1];
                    if (col < HID) {
                        atomicAdd(&out[(size_t)mol * HID + col],     fmaxf(vx + bias[col], 0.f));
                        atomicAdd(&out[(size_t)mol * HID + col + 1], fmaxf(vy + bias[col + 1], 0.f));
                    }
                }
            }
        }
    } else {
        // stage fp16 D in SMEM, then fully-coalesced vector I/O
        __syncthreads();                   // all LDSM of last chunk done
        __half* sh = (__half*)smem;        // 64 x EPI_STRIDE halves = 45056 B
        const int g   = lane >> 2;
        const int tig = lane & 3;
#pragma unroll
        for (int mf = 0; mf < 2; mf++)
#pragma unroll
            for (int h = 0; h < 2; h++) {
                int rl = wm * 32 + mf * 16 + g + h * 8;
#pragma unroll
                for (int j = 0; j < 10; j++) {
                    int col = wn * 80 + j * 8 + tig * 2;
                    *(__half2*)&sh[rl * EPI_STRIDE + col] =
                        __floats2half2_rn(acc[mf][j][h * 2], acc[mf][j][h * 2 + 1]);
                }
            }
        __syncthreads();

        const int r  = tid >> 2;           // 0..63
        const int cp = tid & 3;
        const int gm = m0 + r;
        if (gm < M) {
#pragma unroll
            for (int i = 0; i < 10; i++) {
                int ch = cp + i * 4;       // 16B chunk index 0..39
                uint4 d = *(uint4*)&sh[r * EPI_STRIDE + ch * 8];
                size_t o = (size_t)gm * NPAD + ch * 8;
                if (MODE == 0) {
                    *(uint4*)&dst[o] = d;            // binput16; bmsg recomputed
                } else {
                    uint4 bi = *(const uint4*)&g_binput16[o];
                    __half2* dp = (__half2*)&d;
                    __half2* bp = (__half2*)&bi;
                    uint4 rl; __half2* rp = (__half2*)&rl;
#pragma unroll
                    for (int q = 0; q < 4; q++)
                        rp[q] = __hmax2(__hadd2(bp[q], dp[q]), hz);
                    *(uint4*)&dst[o] = rl;
                }
            }
        }
    }
}

// ---------------------------------------------------------------------------
// gather: amsg[a] = sum_j relu?(src[a2b[a][j]])   (fp32 accumulate, fp16 store)
// ---------------------------------------------------------------------------
template <bool RELU>
__global__ void gather_kernel(const int* __restrict__ a2b,
                              const __half* __restrict__ src)
{
    int atom = blockIdx.x * 6 + threadIdx.y;
    if (atom >= MA) return;
    int tx = threadIdx.x;                 // 0..39, 8 halves each
    const int* row = a2b + (size_t)atom * MAXNB;
    const __half2 z = __floats2half2_rn(0.f, 0.f);
    float2 acc[4] = {{0,0},{0,0},{0,0},{0,0}};
#pragma unroll
    for (int j = 0; j < MAXNB; j++) {
        uint4 v = *(const uint4*)(src + (size_t)row[j] * NPAD + tx * 8);
        __half2* hp = (__half2*)&v;
#pragma unroll
        for (int q = 0; q < 4; q++) {
            __half2 hv = RELU ? __hmax2(hp[q], z) : hp[q];
            float2 f = __half22float2(hv);
            acc[q].x += f.x; acc[q].y += f.y;
        }
    }
    uint4 u;
    __half2* up = (__half2*)&u;
#pragma unroll
    for (int q = 0; q < 4; q++) up[q] = __float22half2_rn(acc[q]);
    *(uint4*)(g_amsg + (size_t)atom * NPAD + tx * 8) = u;
}

// ---------------------------------------------------------------------------
// prep kernels
// ---------------------------------------------------------------------------
__global__ void prep_fb(const float* __restrict__ f_bonds)
{
    long i = blockIdx.x * 256L + threadIdx.x;
    if (i >= (long)MBP * 20) return;
    long m = i / 20; int t = (int)(i % 20);
    int k0 = t * 8;
    __half h[8];
#pragma unroll
    for (int q = 0; q < 8; q++) {
        int k = k0 + q;
        h[q] = (m < MB && k < BFD) ? __float2half_rn(f_bonds[m * BFD + k]) : __half(0.f);
    }
    *(uint4*)(g_fb16 + (size_t)m * 160 + k0) = *(uint4*)h;
}

__global__ void prep_fa(const float* __restrict__ f_atoms)
{
    long i = blockIdx.x * 256L + threadIdx.x;
    if (i >= (long)MAP * 18) return;
    long m = i / 18; int t = (int)(i % 18);
    int k0 = t * 8;
    __half h[8];
#pragma unroll
    for (int q = 0; q < 8; q++) {
        int k = k0 + q;
        h[q] = (m < MA && k < AFD) ? __float2half_rn(f_atoms[m * AFD + k]) : __half(0.f);
    }
    *(uint4*)(g_fa16 + (size_t)m * 144 + k0) = *(uint4*)h;
}

// weights: fp16, k-planar [plane][320][16], swizzle baked per n-row
__global__ void prep_w(const float* __restrict__ Wi, const float* __restrict__ Wh,
                       const float* __restrict__ Wo)
{
    int i = blockIdx.x * 256 + threadIdx.x;
    const int I0 = 320 * 2 * KCH0, I1 = 320 * 2 * KCH1, I2 = 320 * 2 * KCH2;
    if (i >= I0 + I1 + I2) return;
    const float* W; __half* dst; int n, t, which;
    if (i < I0)            { W = Wi; dst = g_wt0; n = i / (2*KCH0); t = i % (2*KCH0); which = 0; }
    else if (i < I0 + I1)  { int j = i - I0; W = Wh; dst = g_wt1; n = j / (2*KCH1); t = j % (2*KCH1); which = 1; }
    else                   { int j = i - I0 - I1; W = Wo; dst = g_wt2; n = j / (2*KCH2); t = j % (2*KCH2); which = 2; }
    int plane = t >> 1, sel = t & 1;
    __half h[8];
#pragma unroll
    for (int q = 0; q < 8; q++) {
        int kk = plane * 16 + sel * 8 + q;
        float v = 0.f;
        if (n < HID) {
            if (which == 0)      { if (kk < BFD) v = W[(size_t)kk * HID + n]; }
            else if (which == 1) { if (kk < HID) v = W[(size_t)kk * HID + n]; }
            else {
                if (plane < 9) { if (kk < AFD) v = W[(size_t)kk * HID + n]; }
                else {
                    int k2 = (plane - 9) * 16 + sel * 8 + q;
                    if (k2 < HID) v = W[(size_t)(AFD + k2) * HID + n];
                }
            }
        }
        h[q] = __float2half_rn(v);
    }
    *(uint4*)(dst + ((size_t)plane * NPAD + n) * 16 + (sel ^ SWZ(n)) * 8) = *(uint4*)h;
}

// ---------------------------------------------------------------------------
__global__ void zero_kernel(float* __restrict__ out)
{
    int i = blockIdx.x * 256 + threadIdx.x;
    if (i < NMOL * HID) out[i] = 0.f;
    if (i < NMOL) g_counts[i] = 0.f;
}
__global__ void count_kernel(const int* __restrict__ mol_ids)
{
    int i = blockIdx.x * 256 + threadIdx.x;
    if (i < N_AT) atomicAdd(&g_counts[mol_ids[i]], 1.f);
}
__global__ void divide_kernel(float* __restrict__ out)
{
    int i = blockIdx.x * 256 + threadIdx.x;
    if (i < NMOL * HID) out[i] = out[i] / fmaxf(g_counts[i / HID], 1.f);
}

// ---------------------------------------------------------------------------
extern "C" void kernel_launch(void* const* d_in, const int* in_sizes, int n_in,
                              void* d_out, int out_size)
{
    const float* f_atoms = (const float*)d_in[0];
    const float* f_bonds = (const float*)d_in[1];
    const float* W_i     = (const float*)d_in[2];
    const float* W_h     = (const float*)d_in[3];
    const float* W_o     = (const float*)d_in[4];
    const float* b_o     = (const float*)d_in[5];
    const int*   a2b     = (const int*)d_in[6];
    const int*   b2a     = (const int*)d_in[7];
    const int*   b2revb  = (const int*)d_in[8];
    const int*   mol_ids = (const int*)d_in[9];
    float* out = (float*)d_out;

    cudaFuncSetAttribute(tc_gemm<0, KCH0, false>, cudaFuncAttributeMaxDynamicSharedMemorySize, SMEM_T);
    cudaFuncSetAttribute(tc_gemm<1, KCH1, true>,  cudaFuncAttributeMaxDynamicSharedMemorySize, SMEM_T);
    cudaFuncSetAttribute(tc_gemm<1, KCH1, false>, cudaFuncAttributeMaxDynamicSharedMemorySize, SMEM_T);
    cudaFuncSetAttribute(tc_gemm<2, KCH2, false>, cudaFuncAttributeMaxDynamicSharedMemorySize, SMEM_T);

    __half *binp, *bmA, *bmB;
    cudaGetSymbolAddress((void**)&binp, g_binput16);
    cudaGetSymbolAddress((void**)&bmA, g_bmsgA);
    cudaGetSymbolAddress((void**)&bmB, g_bmsgB);

    const int gridB = MBP / 64;       // 3126
    const int gridA = MAP / 64;       // 1564
    dim3 gblk(40, 6);
    const int ggA = (MA + 5) / 6;
    const int wItems = 320 * 2 * (KCH0 + KCH1 + KCH2);

    // launch index 3 = tc_gemm<0> (the slot ncu samples)
    prep_fb<<<(int)(((long)MBP * 20 + 255) / 256), 256>>>(f_bonds);        // 0
    prep_w<<<(wItems + 255) / 256, 256>>>(W_i, W_h, W_o);                  // 1
    zero_kernel<<<(NMOL * HID + 255) / 256, 256>>>(out);                   // 2
    tc_gemm<0, KCH0, false><<<gridB, 256, SMEM_T>>>(MB, nullptr, nullptr, nullptr,
                                                    nullptr, nullptr, nullptr, binp); // 3
    prep_fa<<<(int)(((long)MAP * 18 + 255) / 256), 256>>>(f_atoms);        // 4
    count_kernel<<<(N_AT + 255) / 256, 256>>>(mol_ids);                    // 5
    gather_kernel<true><<<ggA, gblk>>>(a2b, binp);                         // 6
    // GEMM1 #1 (fused pre): A = amsg[b2a] - relu(binput16[b2revb]); -> bmsgA
    tc_gemm<1, KCH1, true><<<gridB, 256, SMEM_T>>>(MB, nullptr, nullptr, nullptr,
                                                   b2a, b2revb, binp, bmA); // 7
    gather_kernel<false><<<ggA, gblk>>>(a2b, bmA);                         // 8
    // GEMM1 #2: A = amsg[b2a] - bmsgA[b2revb]; -> bmsgB
    tc_gemm<1, KCH1, false><<<gridB, 256, SMEM_T>>>(MB, nullptr, nullptr, nullptr,
                                                    b2a, b2revb, bmA, bmB); // 9
    gather_kernel<false><<<ggA, gblk>>>(a2b, bmB);                         // 10
    tc_gemm<2, KCH2, false><<<gridA, 256, SMEM_T>>>(MA, b_o, mol_ids, out,
                                                    nullptr, nullptr, nullptr, nullptr); // 11
    divide_kernel<<<(NMOL * HID + 255) / 256, 256>>>(out);                 // 12
}